// round 8
// baseline (speedup 1.0000x reference)
#include <cuda_runtime.h>
#include <cstdint>

#define PATH_NUM 64

// Merge two sorted top-2 value pairs (h>=l) -> exact top-2 of the union,
// duplicate-correct. 4 ops, no selects, no indices.
__device__ __forceinline__ void merge2(float& h, float& l, float h2, float l2) {
    float hi = fmaxf(h, h2);
    float lo = fmaxf(fminf(h, h2), fmaxf(l, l2));
    h = hi; l = lo;
}

__device__ __forceinline__ void top2_of4(float4 v, float& h, float& l) {
    float h1 = fmaxf(v.x, v.y), l1 = fminf(v.x, v.y);
    float h2 = fmaxf(v.z, v.w), l2 = fminf(v.z, v.w);
    h = fmaxf(h1, h2);
    l = fmaxf(fminf(h1, h2), fmaxf(l1, l2));
}

__global__ void __launch_bounds__(256)
topk2_onehot_kernel(const float* __restrict__ score,
                    float* __restrict__ out,
                    int n_rows) {
    const unsigned FULL = 0xFFFFFFFFu;
    int lane    = threadIdx.x & 31;
    int warp_id = blockIdx.x * (blockDim.x >> 5) + (threadIdx.x >> 5);
    int sub     = lane & 7;                 // position within 8-lane row group
    int row     = warp_id * 4 + (lane >> 3);
    bool valid  = row < n_rows;
    int rowc    = valid ? row : (n_rows - 1);   // clamp: all 32 lanes stay converged

    // Lane handles columns {sub*4+p} (j=0) and {32+sub*4+p} (j=1).
    // An 8-lane group covers 128 contiguous bytes per load -> one full line.
    const float4* src = reinterpret_cast<const float4*>(score) + (size_t)rowc * 16;
    float4 a0 = __ldcs(src + sub);
    float4 a1 = __ldcs(src + sub + 8);

    // Local top-2 over the lane's 8 elements
    float h, l, th, tl;
    top2_of4(a0, h, l);
    top2_of4(a1, th, tl); merge2(h, l, th, tl);

    // 8-lane group merge (xor 1,2,4 are group-closed)
    #pragma unroll
    for (int off = 1; off <= 4; off <<= 1) {
        float oh = __shfl_xor_sync(FULL, h, off);
        float ol = __shfl_xor_sync(FULL, l, off);
        merge2(h, l, oh, ol);
    }
    const float m2 = l;   // exact 2nd order statistic of the row

    float vv[8] = {a0.x, a0.y, a0.z, a0.w,  a1.x, a1.y, a1.z, a1.w};

    // Fast path: hot = (v >= m2); group count detects boundary duplicates
    unsigned hotbits = 0;
    #pragma unroll
    for (int e = 0; e < 8; e++)
        hotbits |= (unsigned)(vv[e] >= m2) << e;
    int c = __popc(hotbits);
    c += __shfl_xor_sync(FULL, c, 1);
    c += __shfl_xor_sync(FULL, c, 2);
    c += __shfl_xor_sync(FULL, c, 4);

    if (c != 2) {
        // Rare exact path: duplicates at the top-2 boundary. Keep all v > m2,
        // then the lowest-column elements equal to m2 (jax top_k stability).
        // All 8 lanes of the group enter together (c is group-uniform).
        unsigned gmask = 0xFFu << (lane & ~7);
        int gt = 0;
        unsigned eqflags = 0;
        #pragma unroll
        for (int e = 0; e < 8; e++) {
            gt += (vv[e] > m2);
            if (vv[e] == m2) eqflags |= 1u << e;
        }
        // pack: gt<<8 | eq-count(j=1)<<4 | eq-count(j=0)
        unsigned pack = ((unsigned)gt << 8)
                      | ((unsigned)__popc(eqflags & 0x0Fu))
                      | ((unsigned)__popc((eqflags >> 4) & 0x0Fu) << 4);
        int base = lane & ~7;
        unsigned pk[8];
        #pragma unroll
        for (int s = 0; s < 8; s++)
            pk[s] = __shfl_sync(gmask, pack, base + s);

        int gt_all = 0, eq_j0_all = 0;
        #pragma unroll
        for (int s = 0; s < 8; s++) {
            gt_all    += (int)(pk[s] >> 8);
            eq_j0_all += (int)(pk[s] & 0xFu);
        }

        hotbits = 0;
        // global column = j*32 + sub*4 + p ; element e = j*4 + p
        #pragma unroll
        for (int j = 0; j < 2; j++) {
            int eq_lower_sub = 0;
            #pragma unroll
            for (int s = 0; s < 8; s++)
                if (s < sub) eq_lower_sub += (int)((pk[s] >> (4 * j)) & 0xFu);
            int eq_before_stripe = (j == 1) ? eq_j0_all : 0;
            #pragma unroll
            for (int p = 0; p < 4; p++) {
                int e = j * 4 + p;
                bool isgt = vv[e] > m2;
                bool iseq = (eqflags >> e) & 1u;
                int eq_in_lane_before =
                    __popc(eqflags & ((1u << e) - 1u) & (0xFu << (4 * j)));
                int rank = eq_before_stripe + eq_lower_sub + eq_in_lane_before;
                bool hot = isgt || (iseq && (gt_all + rank) < 2);
                hotbits |= (unsigned)hot << e;
            }
        }
    }

    if (valid) {
        float4* dst = reinterpret_cast<float4*>(out) + (size_t)rowc * 16;
        float4 o0, o1;
        o0.x = (hotbits >> 0) & 1u ? 1.0f : 0.0f;
        o0.y = (hotbits >> 1) & 1u ? 1.0f : 0.0f;
        o0.z = (hotbits >> 2) & 1u ? 1.0f : 0.0f;
        o0.w = (hotbits >> 3) & 1u ? 1.0f : 0.0f;
        o1.x = (hotbits >> 4) & 1u ? 1.0f : 0.0f;
        o1.y = (hotbits >> 5) & 1u ? 1.0f : 0.0f;
        o1.z = (hotbits >> 6) & 1u ? 1.0f : 0.0f;
        o1.w = (hotbits >> 7) & 1u ? 1.0f : 0.0f;
        __stcs(dst + sub,     o0);
        __stcs(dst + sub + 8, o1);
    }
}

extern "C" void kernel_launch(void* const* d_in, const int* in_sizes, int n_in,
                              void* d_out, int out_size) {
    const float* score = (const float*)d_in[0];
    float*       out   = (float*)d_out;

    int n_rows_in  = in_sizes[0] / PATH_NUM;
    int n_rows_out = out_size / PATH_NUM;
    int n_rows = n_rows_in < n_rows_out ? n_rows_in : n_rows_out;

    int warps  = (n_rows + 3) / 4;          // 4 rows per warp
    int blocks = (warps * 32 + 255) / 256;
    topk2_onehot_kernel<<<blocks, 256>>>(score, out, n_rows);
}

// round 9
// speedup vs baseline: 1.0316x; 1.0316x over previous
#include <cuda_runtime.h>
#include <cstdint>

#define PATH_NUM 64

__device__ __forceinline__ void merge2(float& h, float& l, float h2, float l2) {
    float hi = fmaxf(h, h2);
    float lo = fmaxf(fminf(h, h2), fmaxf(l, l2));
    h = hi; l = lo;
}

__device__ __forceinline__ void top2_of4(float4 v, float& h, float& l) {
    float h1 = fmaxf(v.x, v.y), l1 = fminf(v.x, v.y);
    float h2 = fmaxf(v.z, v.w), l2 = fminf(v.z, v.w);
    h = fmaxf(h1, h2);
    l = fmaxf(fminf(h1, h2), fmaxf(l1, l2));
}

// Reduce one row (4-lane group, 16 elems/lane) -> hotbits. R7-proven logic.
__device__ __forceinline__ unsigned row_hotbits(float4 a0, float4 a1,
                                                float4 a2, float4 a3,
                                                int lane, int sub) {
    const unsigned FULL = 0xFFFFFFFFu;
    float h, l, th, tl;
    top2_of4(a0, h, l);
    top2_of4(a1, th, tl); merge2(h, l, th, tl);
    top2_of4(a2, th, tl); merge2(h, l, th, tl);
    top2_of4(a3, th, tl); merge2(h, l, th, tl);

    #pragma unroll
    for (int off = 1; off <= 2; off <<= 1) {
        float oh = __shfl_xor_sync(FULL, h, off);
        float ol = __shfl_xor_sync(FULL, l, off);
        merge2(h, l, oh, ol);
    }
    const float m2 = l;   // exact 2nd order statistic of the row

    float vv[16] = {a0.x, a0.y, a0.z, a0.w,  a1.x, a1.y, a1.z, a1.w,
                    a2.x, a2.y, a2.z, a2.w,  a3.x, a3.y, a3.z, a3.w};

    unsigned hotbits = 0;
    int c = 0;
    #pragma unroll
    for (int e = 0; e < 16; e++) {
        bool hot = vv[e] >= m2;
        hotbits |= (unsigned)hot << e;
        c += hot;
    }
    c += __shfl_xor_sync(FULL, c, 1);
    c += __shfl_xor_sync(FULL, c, 2);

    if (c != 2) {
        // Rare exact path: duplicates at the top-2 boundary. Keep all v > m2,
        // then lowest-column elements equal to m2 (jax top_k stability).
        unsigned gmask = 0xFu << (lane & ~3);
        int gt = 0;
        unsigned eqflags = 0;
        #pragma unroll
        for (int e = 0; e < 16; e++) {
            gt += (vv[e] > m2);
            if (vv[e] == m2) eqflags |= 1u << e;
        }
        unsigned pack = (unsigned)gt << 16;
        #pragma unroll
        for (int j = 0; j < 4; j++)
            pack |= (unsigned)__popc((eqflags >> (4 * j)) & 0xFu) << (4 * j);
        int base = lane & ~3;
        unsigned pk[4];
        #pragma unroll
        for (int s = 0; s < 4; s++)
            pk[s] = __shfl_sync(gmask, pack, base + s);
        int gt_all = (int)((pk[0] >> 16) + (pk[1] >> 16) +
                           (pk[2] >> 16) + (pk[3] >> 16));

        hotbits = 0;
        int eq_before_j = 0;   // eq count in stripes j' < j (all subs)
        #pragma unroll
        for (int j = 0; j < 4; j++) {
            int eq_lower_sub = 0;
            #pragma unroll
            for (int s = 0; s < 4; s++)
                if (s < sub) eq_lower_sub += (int)((pk[s] >> (4 * j)) & 0xFu);
            #pragma unroll
            for (int p = 0; p < 4; p++) {
                int e = j * 4 + p;
                bool isgt = vv[e] > m2;
                bool iseq = (eqflags >> e) & 1u;
                int eq_in_lane_before =
                    __popc(eqflags & ((1u << e) - 1u) & (0xFu << (4 * j)));
                int rank = eq_before_j + eq_lower_sub + eq_in_lane_before;
                bool hot = isgt || (iseq && (gt_all + rank) < 2);
                hotbits |= (unsigned)hot << e;
            }
            int eq_j_all = 0;
            #pragma unroll
            for (int s = 0; s < 4; s++)
                eq_j_all += (int)((pk[s] >> (4 * j)) & 0xFu);
            eq_before_j += eq_j_all;
        }
    }
    return hotbits;
}

__device__ __forceinline__ void store_hot(float* out, size_t row, int sub,
                                          unsigned hotbits) {
    float4* dst = reinterpret_cast<float4*>(out) + row * 16;
    #pragma unroll
    for (int j = 0; j < 4; j++) {
        float4 o;
        o.x = (hotbits >> (j * 4 + 0)) & 1u ? 1.0f : 0.0f;
        o.y = (hotbits >> (j * 4 + 1)) & 1u ? 1.0f : 0.0f;
        o.z = (hotbits >> (j * 4 + 2)) & 1u ? 1.0f : 0.0f;
        o.w = (hotbits >> (j * 4 + 3)) & 1u ? 1.0f : 0.0f;
        __stcs(dst + sub + j * 4, o);
    }
}

__global__ void __launch_bounds__(256)
topk2_onehot_kernel(const float* __restrict__ score,
                    float* __restrict__ out,
                    int n_rows) {
    int lane    = threadIdx.x & 31;
    int warp_id = blockIdx.x * (blockDim.x >> 5) + (threadIdx.x >> 5);
    int sub     = lane & 3;                 // position within 4-lane row group
    int g       = lane >> 2;                // group 0..7

    int rowA = warp_id * 16 + g;            // warp covers 16 rows
    int rowB = rowA + 8;
    bool vA = rowA < n_rows, vB = rowB < n_rows;
    size_t rA = vA ? (size_t)rowA : (size_t)(n_rows - 1);
    size_t rB = vB ? (size_t)rowB : (size_t)(n_rows - 1);

    // Front-batched: 8 independent LDG.128 per thread (MLP=8).
    const float4* srcA = reinterpret_cast<const float4*>(score) + rA * 16;
    const float4* srcB = reinterpret_cast<const float4*>(score) + rB * 16;
    float4 a0 = __ldcs(srcA + sub);
    float4 a1 = __ldcs(srcA + sub + 4);
    float4 a2 = __ldcs(srcA + sub + 8);
    float4 a3 = __ldcs(srcA + sub + 12);
    float4 b0 = __ldcs(srcB + sub);
    float4 b1 = __ldcs(srcB + sub + 4);
    float4 b2 = __ldcs(srcB + sub + 8);
    float4 b3 = __ldcs(srcB + sub + 12);

    unsigned hotA = row_hotbits(a0, a1, a2, a3, lane, sub);
    if (vA) store_hot(out, rA, sub, hotA);

    unsigned hotB = row_hotbits(b0, b1, b2, b3, lane, sub);
    if (vB) store_hot(out, rB, sub, hotB);
}

extern "C" void kernel_launch(void* const* d_in, const int* in_sizes, int n_in,
                              void* d_out, int out_size) {
    const float* score = (const float*)d_in[0];
    float*       out   = (float*)d_out;

    int n_rows_in  = in_sizes[0] / PATH_NUM;
    int n_rows_out = out_size / PATH_NUM;
    int n_rows = n_rows_in < n_rows_out ? n_rows_in : n_rows_out;

    int warps  = (n_rows + 15) / 16;        // 16 rows per warp (2 per thread-group pass)
    int blocks = (warps * 32 + 255) / 256;
    topk2_onehot_kernel<<<blocks, 256>>>(score, out, n_rows);
}